// round 1
// baseline (speedup 1.0000x reference)
#include <cuda_runtime.h>
#include <math_constants.h>

// Problem shape (fixed by the reference: [16, 17, 384, 384] fp32)
#define HM_W 384
#define HM_H 384
#define HM_PLANES (16 * 17)   // 272
#define BAND 48               // rows per block
#define BANDS (HM_H / BAND)   // 8
#define TPB (HM_W / 4)        // 96 threads, one float4 column each

#define SIG_THRESH 0.05f

__device__ __forceinline__ float max3(float a, float b, float c) {
    return fmaxf(a, fmaxf(b, c));
}

__global__ __launch_bounds__(TPB)
void heatmap_peaks_kernel(const float* __restrict__ in, float* __restrict__ out) {
    const int plane = blockIdx.y;
    const int band  = blockIdx.x;
    const int x4    = threadIdx.x * 4;

    const float* __restrict__ p = in  + (size_t)plane * (HM_W * HM_H);
    float* __restrict__       o = out + (size_t)plane * (HM_W * HM_H);

    const bool has_left  = (x4 > 0);
    const bool has_right = (x4 + 4 < HM_W);
    const float NEG = -CUDART_INF_F;

    const int r0 = band * BAND;

    // Carried rows: prev / cur / next, each as (left scalar, float4, right scalar)
    float4 cP, cC, cN;
    float  lP, lC, lN, rP, rC, rN;

    // --- load row r0-1 into P ---
    if (r0 - 1 >= 0) {
        const float* rp = p + (size_t)(r0 - 1) * HM_W + x4;
        cP = *(const float4*)rp;
        lP = has_left  ? __ldg(rp - 1) : NEG;
        rP = has_right ? __ldg(rp + 4) : NEG;
    } else {
        cP = make_float4(NEG, NEG, NEG, NEG); lP = NEG; rP = NEG;
    }
    // --- load row r0 into C (always in range) ---
    {
        const float* rp = p + (size_t)r0 * HM_W + x4;
        cC = *(const float4*)rp;
        lC = has_left  ? __ldg(rp - 1) : NEG;
        rC = has_right ? __ldg(rp + 4) : NEG;
    }

    #pragma unroll 4
    for (int row = r0; row < r0 + BAND; ++row) {
        // --- load row row+1 into N ---
        const int rn = row + 1;
        if (rn < HM_H) {
            const float* rp = p + (size_t)rn * HM_W + x4;
            cN = *(const float4*)rp;
            lN = has_left  ? __ldg(rp - 1) : NEG;
            rN = has_right ? __ldg(rp + 4) : NEG;
        } else {
            cN = make_float4(NEG, NEG, NEG, NEG); lN = NEG; rN = NEG;
        }

        // vertical 3-max per column
        float vl = max3(lP, lC, lN);
        float v0 = max3(cP.x, cC.x, cN.x);
        float v1 = max3(cP.y, cC.y, cN.y);
        float v2 = max3(cP.z, cC.z, cN.z);
        float v3 = max3(cP.w, cC.w, cN.w);
        float vr = max3(rP, rC, rN);

        // horizontal 3-max -> full 3x3 window max
        float m0 = max3(vl, v0, v1);
        float m1 = max3(v0, v1, v2);
        float m2 = max3(v1, v2, v3);
        float m3 = max3(v2, v3, vr);

        // peak test + sigmoid only where candidate peak
        float4 res;
        {
            float x = cC.x; float v = 0.0f;
            if (m0 == x) { float pb = 1.0f / (1.0f + expf(-x)); if (pb > SIG_THRESH) v = pb; }
            res.x = v;
        }
        {
            float x = cC.y; float v = 0.0f;
            if (m1 == x) { float pb = 1.0f / (1.0f + expf(-x)); if (pb > SIG_THRESH) v = pb; }
            res.y = v;
        }
        {
            float x = cC.z; float v = 0.0f;
            if (m2 == x) { float pb = 1.0f / (1.0f + expf(-x)); if (pb > SIG_THRESH) v = pb; }
            res.z = v;
        }
        {
            float x = cC.w; float v = 0.0f;
            if (m3 == x) { float pb = 1.0f / (1.0f + expf(-x)); if (pb > SIG_THRESH) v = pb; }
            res.w = v;
        }

        *(float4*)(o + (size_t)row * HM_W + x4) = res;

        // rotate carried rows
        cP = cC; lP = lC; rP = rC;
        cC = cN; lC = lN; rC = rN;
    }
}

extern "C" void kernel_launch(void* const* d_in, const int* in_sizes, int n_in,
                              void* d_out, int out_size) {
    (void)in_sizes; (void)n_in; (void)out_size;
    const float* heatmaps = (const float*)d_in[0];
    float* out = (float*)d_out;

    dim3 grid(BANDS, HM_PLANES);
    dim3 block(TPB);
    heatmap_peaks_kernel<<<grid, block>>>(heatmaps, out);
}

// round 2
// speedup vs baseline: 1.3079x; 1.3079x over previous
#include <cuda_runtime.h>
#include <math_constants.h>

// Fixed problem shape: [16, 17, 384, 384] fp32
#define HM_W 384
#define HM_H 384
#define HM_PLANES 272
#define BAND 32
#define BANDS (HM_H / BAND)          // 12
#define WARPS 4
#define TPB (WARPS * 32)             // 128
#define NUNITS (HM_PLANES * BANDS)   // 3264
#define NBLOCKS (NUNITS / WARPS)     // 816

#define SIG_THRESH 0.05f
#define FULLM 0xffffffffu

__device__ __forceinline__ float max3(float a, float b, float c) {
    return fmaxf(a, fmaxf(b, c));
}

__device__ __forceinline__ float4 max3v(const float4& a, const float4& b, const float4& c) {
    float4 r;
    r.x = max3(a.x, b.x, c.x);
    r.y = max3(a.y, b.y, c.y);
    r.z = max3(a.z, b.z, c.z);
    r.w = max3(a.w, b.w, c.w);
    return r;
}

// peak score: sigmoid(x) if (3x3 max == x) && sigmoid(x) > 0.05, else 0
__device__ __forceinline__ float peak(float m, float x) {
    float e = __expf(-x);
    float s = __fdividef(1.0f, 1.0f + e);
    return (m == x && s > SIG_THRESH) ? s : 0.0f;
}

__device__ __forceinline__ float4 peaks4(const float4& c, const float4& v,
                                         float vl, float vr) {
    float4 r;
    r.x = peak(max3(vl,  v.x, v.y), c.x);
    r.y = peak(max3(v.x, v.y, v.z), c.y);
    r.z = peak(max3(v.y, v.z, v.w), c.z);
    r.w = peak(max3(v.z, v.w, vr),  c.w);
    return r;
}

__global__ __launch_bounds__(TPB, 6)
void heatmap_peaks_kernel(const float* __restrict__ in, float* __restrict__ out) {
    const int lane = threadIdx.x & 31;
    const int warp = threadIdx.x >> 5;
    const int unit = blockIdx.x * WARPS + warp;

    const int plane = unit / BANDS;
    const int band  = unit - plane * BANDS;

    const float* __restrict__ p = in  + (size_t)plane * (HM_W * HM_H);
    float* __restrict__       o = out + (size_t)plane * (HM_W * HM_H);

    const int r0 = band * BAND;
    const int xb = lane * 4;
    const float NEG = -CUDART_INF_F;
    const float4 NEG4 = make_float4(NEG, NEG, NEG, NEG);

    // Carried rows P (prev), C (cur). Each covers the full row width in 3
    // coalesced float4 chunks: columns xb, xb+128, xb+256.
    float4 P0, P1, P2, C0, C1, C2;

    if (r0 > 0) {
        const float* rp = p + (size_t)(r0 - 1) * HM_W + xb;
        P0 = *(const float4*)(rp);
        P1 = *(const float4*)(rp + 128);
        P2 = *(const float4*)(rp + 256);
    } else {
        P0 = NEG4; P1 = NEG4; P2 = NEG4;
    }
    {
        const float* rp = p + (size_t)r0 * HM_W + xb;
        C0 = *(const float4*)(rp);
        C1 = *(const float4*)(rp + 128);
        C2 = *(const float4*)(rp + 256);
    }

    const float* np = p + (size_t)(r0 + 1) * HM_W + xb;   // next-row pointer
    float*       op = o + (size_t)r0 * HM_W + xb;         // output-row pointer

    #pragma unroll 4
    for (int r = r0; r < r0 + BAND; ++r) {
        // Prefetch next row (independent of compute below)
        float4 N0, N1, N2;
        if (r + 1 < HM_H) {
            N0 = *(const float4*)(np);
            N1 = *(const float4*)(np + 128);
            N2 = *(const float4*)(np + 256);
        } else {
            N0 = NEG4; N1 = NEG4; N2 = NEG4;
        }
        np += HM_W;

        // Vertical 3-max per column (component-wise)
        float4 v0 = max3v(P0, C0, N0);
        float4 v1 = max3v(P1, C1, N1);
        float4 v2 = max3v(P2, C2, N2);

        // Horizontal neighbors via warp shuffles.
        // Left neighbor of chunk j lane l is chunk j lane l-1 (.w);
        // for lane 0 it is chunk j-1 lane 31 (.w), or -inf for j=0.
        float l0 = __shfl_up_sync(FULLM, v0.w, 1);
        float l1 = __shfl_up_sync(FULLM, v1.w, 1);
        float l2 = __shfl_up_sync(FULLM, v2.w, 1);
        float b01 = __shfl_sync(FULLM, v0.w, 31);
        float b12 = __shfl_sync(FULLM, v1.w, 31);
        // Right neighbor: chunk j lane l+1 (.x); lane 31 takes chunk j+1 lane 0.
        float r0s = __shfl_down_sync(FULLM, v0.x, 1);
        float r1s = __shfl_down_sync(FULLM, v1.x, 1);
        float r2s = __shfl_down_sync(FULLM, v2.x, 1);
        float f10 = __shfl_sync(FULLM, v1.x, 0);
        float f21 = __shfl_sync(FULLM, v2.x, 0);

        if (lane == 0)  { l0 = NEG; l1 = b01; l2 = b12; }
        if (lane == 31) { r0s = f10; r1s = f21; r2s = NEG; }

        // Peak test + sigmoid, store row
        float4 o0 = peaks4(C0, v0, l0, r0s);
        float4 o1 = peaks4(C1, v1, l1, r1s);
        float4 o2 = peaks4(C2, v2, l2, r2s);

        *(float4*)(op)       = o0;
        *(float4*)(op + 128) = o1;
        *(float4*)(op + 256) = o2;
        op += HM_W;

        // Rotate carried rows
        P0 = C0; P1 = C1; P2 = C2;
        C0 = N0; C1 = N1; C2 = N2;
    }
}

extern "C" void kernel_launch(void* const* d_in, const int* in_sizes, int n_in,
                              void* d_out, int out_size) {
    (void)in_sizes; (void)n_in; (void)out_size;
    const float* heatmaps = (const float*)d_in[0];
    float* out = (float*)d_out;

    heatmap_peaks_kernel<<<NBLOCKS, TPB>>>(heatmaps, out);
}